// round 13
// baseline (speedup 1.0000x reference)
#include <cuda_runtime.h>
#include <cuda_bf16.h>
#include <math.h>
#include <stdint.h>

// Problem constants
#define BATCH 8
#define SEQ 1024
#define DIM 1024
#define NHEADS 16
#define HDIM 64
#define M_TOK (BATCH * SEQ)        // 8192
#define QKV_COLS (3 * DIM)         // 3072
#define ATT_SCALE 0.125f           // 64^-0.5

#if defined(__CUDA_ARCH__) && defined(__CUDA_ARCH_FEAT_SM103_ALL)
#define HAS_TCGEN05 1
#else
#define HAS_TCGEN05 0
#endif

// Scratch (allocation-free rule: __device__ globals)
__device__ float g_qkv[(size_t)M_TOK * QKV_COLS];        // 96 MB
__device__ float g_att[(size_t)M_TOK * DIM];             // 32 MB
__device__ float g_wt[(size_t)(QKV_COLS + DIM) * DIM];   // 16 MB: wqkvT | wprojT

// ===========================================================================
// tcgen05 helpers
// ===========================================================================
__device__ __forceinline__ uint32_t smem_u32(const void* p) {
    uint32_t a;
    asm("{ .reg .u64 t; cvta.to.shared.u64 t, %1; cvt.u32.u64 %0, t; }"
        : "=r"(a) : "l"(p));
    return a;
}

__device__ __forceinline__ uint32_t elect_one() {
    uint32_t pred;
    asm volatile(
        "{\n\t.reg .pred p;\n\t"
        "elect.sync _|p, 0xFFFFFFFF;\n\t"
        "selp.b32 %0, 1, 0, p;\n\t}"
        : "=r"(pred));
    return pred;
}

// SW128 K-major smem descriptor: layout=SW128(2), version=1, SBO=64, LBO=1
__device__ __forceinline__ uint64_t make_desc_sw128(uint32_t addr) {
    const uint64_t base =
        (uint64_t(2) << 61) | (uint64_t(1) << 46) |
        (uint64_t(64) << 32) | (uint64_t(1) << 16);
    return base | ((uint64_t)(addr >> 4) & 0x3FFF);
}

#define SWZ128(off) ((off) ^ (((off) >> 3) & 0x70))

#if HAS_TCGEN05
__device__ __forceinline__ void mma_tf32_ss(uint32_t d, uint64_t ad, uint64_t bd,
                                            uint32_t idesc, uint32_t en) {
    asm volatile(
        "{\n\t.reg .pred p;\n\t"
        "setp.ne.u32 p, %5, 0;\n\t"
        "tcgen05.mma.cta_group::1.kind::tf32 [%0], %1, %2, %3, {%4,%4,%4,%4}, p;\n\t"
        "}"
        :: "r"(d), "l"(ad), "l"(bd), "r"(idesc), "r"(0u), "r"(en)
        : "memory");
}

__device__ __forceinline__ void mma_tf32_ts(uint32_t d, uint32_t at, uint64_t bd,
                                            uint32_t idesc, uint32_t en) {
    asm volatile(
        "{\n\t.reg .pred p;\n\t"
        "setp.ne.u32 p, %5, 0;\n\t"
        "tcgen05.mma.cta_group::1.kind::tf32 [%0], [%1], %2, %3, {%4,%4,%4,%4}, p;\n\t"
        "}"
        :: "r"(d), "r"(at), "l"(bd), "r"(idesc), "r"(0u), "r"(en)
        : "memory");
}

#define TC_ALLOC(sm, n)  asm volatile("tcgen05.alloc.cta_group::1.sync.aligned.shared::cta.b32 [%0], %1;" :: "r"(sm), "r"((uint32_t)(n)) : "memory")
#define TC_DEALLOC(t, n) asm volatile("tcgen05.dealloc.cta_group::1.sync.aligned.b32 %0, %1;" :: "r"(t), "r"((uint32_t)(n)))
#define TC_RELINQ()      asm volatile("tcgen05.relinquish_alloc_permit.cta_group::1.sync.aligned;")
#define TC_COMMIT(mb)    asm volatile("tcgen05.commit.cta_group::1.mbarrier::arrive::one.shared::cluster.b64 [%0];" :: "r"(mb) : "memory")
#define TC_FENCE_BEFORE() asm volatile("tcgen05.fence::before_thread_sync;" ::: "memory")
#define TC_FENCE_AFTER() asm volatile("tcgen05.fence::after_thread_sync;" ::: "memory")
#define TC_WAIT_LD()     asm volatile("tcgen05.wait::ld.sync.aligned;" ::: "memory")
#define TC_WAIT_ST()     asm volatile("tcgen05.wait::st.sync.aligned;" ::: "memory")

#define TMEM_LDX32(r, ta)                                                   \
    asm volatile(                                                           \
        "tcgen05.ld.sync.aligned.32x32b.x32.b32 "                           \
        "{%0,%1,%2,%3,%4,%5,%6,%7,%8,%9,%10,%11,%12,%13,%14,%15,"           \
        "%16,%17,%18,%19,%20,%21,%22,%23,%24,%25,%26,%27,%28,%29,%30,%31}, [%32];" \
        : "=r"((r)[0]),"=r"((r)[1]),"=r"((r)[2]),"=r"((r)[3]),              \
          "=r"((r)[4]),"=r"((r)[5]),"=r"((r)[6]),"=r"((r)[7]),              \
          "=r"((r)[8]),"=r"((r)[9]),"=r"((r)[10]),"=r"((r)[11]),            \
          "=r"((r)[12]),"=r"((r)[13]),"=r"((r)[14]),"=r"((r)[15]),          \
          "=r"((r)[16]),"=r"((r)[17]),"=r"((r)[18]),"=r"((r)[19]),          \
          "=r"((r)[20]),"=r"((r)[21]),"=r"((r)[22]),"=r"((r)[23]),          \
          "=r"((r)[24]),"=r"((r)[25]),"=r"((r)[26]),"=r"((r)[27]),          \
          "=r"((r)[28]),"=r"((r)[29]),"=r"((r)[30]),"=r"((r)[31])           \
        : "r"(ta))

#define TMEM_STX32(ta, r)                                                   \
    asm volatile(                                                           \
        "tcgen05.st.sync.aligned.32x32b.x32.b32 [%0], "                     \
        "{%1,%2,%3,%4,%5,%6,%7,%8,%9,%10,%11,%12,%13,%14,%15,%16,"          \
        "%17,%18,%19,%20,%21,%22,%23,%24,%25,%26,%27,%28,%29,%30,%31,%32};" \
        :: "r"(ta),                                                         \
           "r"((r)[0]),"r"((r)[1]),"r"((r)[2]),"r"((r)[3]),                 \
           "r"((r)[4]),"r"((r)[5]),"r"((r)[6]),"r"((r)[7]),                 \
           "r"((r)[8]),"r"((r)[9]),"r"((r)[10]),"r"((r)[11]),               \
           "r"((r)[12]),"r"((r)[13]),"r"((r)[14]),"r"((r)[15]),             \
           "r"((r)[16]),"r"((r)[17]),"r"((r)[18]),"r"((r)[19]),             \
           "r"((r)[20]),"r"((r)[21]),"r"((r)[22]),"r"((r)[23]),             \
           "r"((r)[24]),"r"((r)[25]),"r"((r)[26]),"r"((r)[27]),             \
           "r"((r)[28]),"r"((r)[29]),"r"((r)[30]),"r"((r)[31])              \
        : "memory")
#endif // HAS_TCGEN05

#define MBAR_INIT(mb, n) asm volatile("mbarrier.init.shared.b64 [%0], %1;" :: "r"(mb), "r"((uint32_t)(n)) : "memory")
#define FENCE_PROXY()    asm volatile("fence.proxy.async.shared::cta;" ::: "memory")

#define MBAR_WAIT(mb, ph) do {                                              \
    uint32_t _m = (mb), _p = (ph), _done;                                   \
    asm volatile(                                                           \
        "{\n\t.reg .pred p;\n\t"                                            \
        "mbarrier.try_wait.parity.acquire.cta.shared::cta.b64 p, [%1], %2;\n\t" \
        "selp.b32 %0, 1, 0, p;\n\t}"                                        \
        : "=r"(_done) : "r"(_m), "r"(_p) : "memory");                       \
    if (!_done) {                                                           \
        asm volatile(                                                       \
            "{\n\t.reg .pred P1;\n\t"                                       \
            "WL_%=:\n\t"                                                    \
            "mbarrier.try_wait.parity.acquire.cta.shared::cta.b64 P1, [%0], %1, 0x989680;\n\t" \
            "@P1 bra.uni WD_%=;\n\t"                                        \
            "bra.uni WL_%=;\n\t"                                            \
            "WD_%=:\n\t}"                                                   \
            :: "r"(_m), "r"(_p) : "memory");                                \
    }                                                                       \
} while (0)

__device__ __forceinline__ float f2tf32(float v) {
    unsigned int u;
    asm volatile("cvt.rna.tf32.f32 %0, %1;" : "=r"(u) : "f"(v));
    return __uint_as_float(u);
}

// ===========================================================================
// Weight pre-transpose: W[K][N] -> WT[N][K], tf32-converted. Run once/launch.
// ===========================================================================
__global__ __launch_bounds__(256) void transpose_tf32(
    const float* __restrict__ W, float* __restrict__ WT, int K, int N)
{
    __shared__ float tile[32][33];
    const int n0 = blockIdx.x * 32;
    const int k0 = blockIdx.y * 32;
    const int tx = threadIdx.x & 31;
    const int ty = threadIdx.x >> 5;

    #pragma unroll
    for (int i = ty; i < 32; i += 8)
        tile[i][tx] = W[(size_t)(k0 + i) * N + n0 + tx];
    __syncthreads();
    #pragma unroll
    for (int i = ty; i < 32; i += 8)
        WT[(size_t)(n0 + i) * K + k0 + tx] = f2tf32(tile[tx][i]);
}

// ===========================================================================
// tcgen05 tf32 GEMM, TS mode: C[M,N] = A[M,K] @ BT[N,K]^T + bias[N].
// Tile 128x256, BK=64, 256 threads.
//  - A lives in TMEM (double-buffered, cols 0..127; 8 cols per K-step).
//  - B (pre-transposed tf32) double-buffered in smem, blocked SW128 atoms:
//    256 rows x 64 floats; atom-col stride 32768B; K-step desc offsets
//    2s (s<4), 2048+2(s-4) (s>=4).
//  - D in TMEM cols 128..383.
// ===========================================================================
#define BM 128
#define BN 256
#define GBK 64
#define GB0 0
#define GB1 65536
#define GEMM_SMEM 131072

__global__ __launch_bounds__(256, 1) __cluster_dims__(1, 1, 1)
void gemm_tc_tf32(const float* __restrict__ A, const float* __restrict__ BT,
                  const float* __restrict__ bias, float* __restrict__ C,
                  int M, int N, int K)
{
#if HAS_TCGEN05
    extern __shared__ __align__(1024) char dsm[];
    __shared__ uint32_t s_tmem;
    __shared__ __align__(8) uint64_t s_mbar[2];

    const int tid = threadIdx.x;
    const int brow = blockIdx.y * BM;
    const int bcol = blockIdx.x * BN;
    const uint32_t smb = smem_u32(dsm);
    const uint32_t mbar0 = smem_u32(&s_mbar[0]);
    const uint32_t mbar1 = smem_u32(&s_mbar[1]);

    if (tid < 32) TC_ALLOC(smem_u32(&s_tmem), 512);
    if (tid == 0) { MBAR_INIT(mbar0, 1); MBAR_INIT(mbar1, 1); }
    __syncthreads();
    const uint32_t tmem = s_tmem;
    const uint32_t TD = tmem + 128;       // D: 256 cols

    const uint32_t idesc = (1u << 4) | (2u << 7) | (2u << 10)
                         | ((BN / 8) << 17) | ((BM / 16) << 24);
    const int nch = K / GBK;   // 16

    // ---- A mapping: thread = (row 0..127, khalf 0..1), 32 k-values each ----
    const int arow = tid & 127;
    const int kh   = tid >> 7;            // 0: k 0-31, 1: k 32-63
    const uint32_t awoff = (uint32_t)((tid & 127) >> 5) << 21;

    // ---- B mapping: 16 float4 per thread over [256 rows][64 floats] ----
    uint32_t bsoff[16];
    int brI[16], bcI[16];
    #pragma unroll
    for (int i = 0; i < 16; i++) {
        int id = i * 256 + tid;           // 0..4095
        int r = id >> 4;                  // 0..255
        int c = (id & 15) * 4;            // 0..60 floats
        brI[i] = r; bcI[i] = c;
        uint32_t off = (uint32_t)(((c >> 5) * 32 + (r >> 3)) * 1024
                                  + (r & 7) * 128 + (c & 31) * 4);
        bsoff[i] = SWZ128(off);
    }

    // ---- prefetch chunk 0 ----
    float4 av[8];
    float4 bv[16];
    #pragma unroll
    for (int j = 0; j < 8; j++)
        av[j] = *reinterpret_cast<const float4*>(
            A + (size_t)(brow + arow) * K + kh * 32 + j * 4);
    #pragma unroll
    for (int i = 0; i < 16; i++)
        bv[i] = *reinterpret_cast<const float4*>(
            BT + (size_t)(bcol + brI[i]) * K + bcI[i]);

    for (int ch = 0; ch < nch; ch++) {
        const int b = ch & 1;
        const uint32_t bbuf = smb + (b ? GB1 : GB0);
        const uint32_t abuf = tmem + b * 64;

        if (ch >= 2) MBAR_WAIT(b ? mbar1 : mbar0, ((ch >> 1) - 1) & 1);

        // ---- A -> TMEM (tf32) ----
        {
            uint32_t u[32];
            #pragma unroll
            for (int j = 0; j < 8; j++) {
                u[j * 4 + 0] = __float_as_uint(f2tf32(av[j].x));
                u[j * 4 + 1] = __float_as_uint(f2tf32(av[j].y));
                u[j * 4 + 2] = __float_as_uint(f2tf32(av[j].z));
                u[j * 4 + 3] = __float_as_uint(f2tf32(av[j].w));
            }
            TMEM_STX32(abuf + kh * 32 + awoff, u);
            TC_WAIT_ST();
        }

        // ---- B -> smem ----
        #pragma unroll
        for (int i = 0; i < 16; i++) {
            asm volatile("st.shared.v4.b32 [%0], {%1,%2,%3,%4};"
                :: "r"(bbuf + bsoff[i]),
                   "r"(__float_as_uint(bv[i].x)), "r"(__float_as_uint(bv[i].y)),
                   "r"(__float_as_uint(bv[i].z)), "r"(__float_as_uint(bv[i].w))
                : "memory");
        }

        // ---- prefetch next chunk ----
        if (ch + 1 < nch) {
            const int k0 = (ch + 1) * GBK;
            #pragma unroll
            for (int j = 0; j < 8; j++)
                av[j] = *reinterpret_cast<const float4*>(
                    A + (size_t)(brow + arow) * K + k0 + kh * 32 + j * 4);
            #pragma unroll
            for (int i = 0; i < 16; i++)
                bv[i] = *reinterpret_cast<const float4*>(
                    BT + (size_t)(bcol + brI[i]) * K + k0 + bcI[i]);
        }

        TC_FENCE_BEFORE();
        FENCE_PROXY();
        __syncthreads();

        if (tid < 32) {
            if (elect_one()) {
                TC_FENCE_AFTER();
                uint64_t bd = make_desc_sw128(bbuf);
                #pragma unroll
                for (int s = 0; s < 8; s++) {
                    uint64_t dso = (uint64_t)((s & 3) * 2 + (s >> 2) * 2048);
                    mma_tf32_ts(TD, abuf + s * 8, bd + dso, idesc,
                                (ch | s) != 0);
                }
                TC_COMMIT(b ? mbar1 : mbar0);
            }
        }
    }

    {
        const int last = nch - 1;
        MBAR_WAIT((last & 1) ? mbar1 : mbar0, (last >> 1) & 1);
    }
    TC_FENCE_AFTER();

    // ---- epilogue: 256 threads, wg0 cols 0-127, wg1 cols 128-255 ----
    {
        const int row = tid & 127;
        const int wh  = tid >> 7;
        const int crow = brow + row;
        #pragma unroll
        for (int c0 = 0; c0 < 128; c0 += 32) {
            uint32_t d[32];
            TMEM_LDX32(d, TD + wh * 128 + c0);
            TC_WAIT_LD();
            const int cb = bcol + wh * 128 + c0;
            #pragma unroll
            for (int c = 0; c < 32; c += 4) {
                float4 v;
                v.x = __uint_as_float(d[c + 0]) + bias[cb + c + 0];
                v.y = __uint_as_float(d[c + 1]) + bias[cb + c + 1];
                v.z = __uint_as_float(d[c + 2]) + bias[cb + c + 2];
                v.w = __uint_as_float(d[c + 3]) + bias[cb + c + 3];
                *reinterpret_cast<float4*>(C + (size_t)crow * N + cb + c) = v;
            }
        }
    }
    __syncthreads();
    if (tid < 32) {
        TC_RELINQ();
        TC_DEALLOC(tmem, 512);
    }
#endif // HAS_TCGEN05
}

// ===========================================================================
// Tensor-core flash attention (unchanged from round 11 — 167us proven).
// ===========================================================================
#define AQ_OFF 0
#define AK_OFF(buf) (32768 + (buf) * 32768)
#define AV_OFF(buf) (98304 + (buf) * 32768)
#define ATT_SMEM 163840

__global__ __launch_bounds__(256, 1) __cluster_dims__(1, 1, 1)
void attn_tc(const float* __restrict__ qkv, float* __restrict__ out)
{
#if HAS_TCGEN05
    extern __shared__ __align__(1024) char dsm[];
    __shared__ uint32_t s_tmem;
    __shared__ __align__(8) uint64_t s_mb[2];
    __shared__ float s_l[256];

    const int tid = threadIdx.x;
    const int qt = blockIdx.x;
    const int h  = blockIdx.y;
    const int b  = blockIdx.z;
    const uint32_t smb = smem_u32(dsm);
    const uint32_t mb_s = smem_u32(&s_mb[0]);
    const uint32_t mb_o = smem_u32(&s_mb[1]);

    if (tid < 32) TC_ALLOC(smem_u32(&s_tmem), 256);
    if (tid == 0) { MBAR_INIT(mb_s, 1); MBAR_INIT(mb_o, 1); }
    __syncthreads();
    const uint32_t tmem = s_tmem;
    const uint32_t TS = tmem;            // S cols [0,128); P in place
    const uint32_t TO = tmem + 128;      // O cols [128,192)

    const size_t tokQ = (size_t)b * SEQ + qt * 128;
    const size_t tokB = (size_t)b * SEQ;

    const uint32_t idescS = (1u << 4) | (2u << 7) | (2u << 10)
                          | (16u << 17) | (8u << 24);
    const uint32_t idescO = (1u << 4) | (2u << 7) | (2u << 10)
                          | (8u << 17) | (8u << 24);

    int rI[8], cI[8];
    #pragma unroll
    for (int i = 0; i < 8; i++) {
        int id = i * 256 + tid;
        rI[i] = id >> 4;
        cI[i] = (id & 15) * 4;
    }

    #pragma unroll
    for (int i = 0; i < 8; i++) {
        float4 v = *reinterpret_cast<const float4*>(
            qkv + (tokQ + rI[i]) * QKV_COLS + h * HDIM + cI[i]);
        uint32_t off = AQ_OFF + (cI[i] >> 5) * 16384
                     + SWZ128((uint32_t)(rI[i] * 128 + (cI[i] & 31) * 4));
        asm volatile("st.shared.v4.b32 [%0], {%1,%2,%3,%4};"
            :: "r"(smb + off),
               "r"(__float_as_uint(f2tf32(v.x * ATT_SCALE))),
               "r"(__float_as_uint(f2tf32(v.y * ATT_SCALE))),
               "r"(__float_as_uint(f2tf32(v.z * ATT_SCALE))),
               "r"(__float_as_uint(f2tf32(v.w * ATT_SCALE))) : "memory");
    }

    float4 kreg[8], vreg[8];
    #pragma unroll
    for (int i = 0; i < 8; i++) {
        const float* base = qkv + (tokB + rI[i]) * QKV_COLS + h * HDIM + cI[i];
        kreg[i] = *reinterpret_cast<const float4*>(base + DIM);
        vreg[i] = *reinterpret_cast<const float4*>(base + 2 * DIM);
    }

    float lsum = 0.f;

    for (int t = 0; t < 8; t++) {
        const int buf = t & 1;

        #pragma unroll
        for (int i = 0; i < 8; i++) {
            uint32_t koff = AK_OFF(buf) + (cI[i] >> 5) * 16384
                          + SWZ128((uint32_t)(rI[i] * 128 + (cI[i] & 31) * 4));
            asm volatile("st.shared.v4.b32 [%0], {%1,%2,%3,%4};"
                :: "r"(smb + koff),
                   "r"(__float_as_uint(f2tf32(kreg[i].x))),
                   "r"(__float_as_uint(f2tf32(kreg[i].y))),
                   "r"(__float_as_uint(f2tf32(kreg[i].z))),
                   "r"(__float_as_uint(f2tf32(kreg[i].w))) : "memory");
            uint32_t kb  = (rI[i] >> 5) * 8192;
            uint32_t kc4 = (rI[i] & 31) * 4;
            uint32_t o0 = AV_OFF(buf) + kb + SWZ128((uint32_t)((cI[i] + 0) * 128 + kc4));
            uint32_t o1 = AV_OFF(buf) + kb + SWZ128((uint32_t)((cI[i] + 1) * 128 + kc4));
            uint32_t o2 = AV_OFF(buf) + kb + SWZ128((uint32_t)((cI[i] + 2) * 128 + kc4));
            uint32_t o3 = AV_OFF(buf) + kb + SWZ128((uint32_t)((cI[i] + 3) * 128 + kc4));
            asm volatile("st.shared.b32 [%0], %1;" :: "r"(smb + o0),
                         "r"(__float_as_uint(f2tf32(vreg[i].x))) : "memory");
            asm volatile("st.shared.b32 [%0], %1;" :: "r"(smb + o1),
                         "r"(__float_as_uint(f2tf32(vreg[i].y))) : "memory");
            asm volatile("st.shared.b32 [%0], %1;" :: "r"(smb + o2),
                         "r"(__float_as_uint(f2tf32(vreg[i].z))) : "memory");
            asm volatile("st.shared.b32 [%0], %1;" :: "r"(smb + o3),
                         "r"(__float_as_uint(f2tf32(vreg[i].w))) : "memory");
        }
        FENCE_PROXY();
        __syncthreads();

        if (tid < 32) {
            if (t > 0) MBAR_WAIT(mb_o, (t - 1) & 1);
            if (elect_one()) {
                #pragma unroll
                for (int s = 0; s < 8; s++) {
                    uint64_t ad = make_desc_sw128(smb + AQ_OFF + (s >> 2) * 16384)
                                + (uint64_t)(s & 3) * 2;
                    uint64_t bd = make_desc_sw128(smb + AK_OFF(buf) + (s >> 2) * 16384)
                                + (uint64_t)(s & 3) * 2;
                    mma_tf32_ss(TS, ad, bd, idescS, s != 0);
                }
                TC_COMMIT(mb_s);
            }
        }

        if (t + 1 < 8) {
            #pragma unroll
            for (int i = 0; i < 8; i++) {
                const float* base = qkv + (tokB + (t + 1) * 128 + rI[i]) * QKV_COLS
                                  + h * HDIM + cI[i];
                kreg[i] = *reinterpret_cast<const float4*>(base + DIM);
                vreg[i] = *reinterpret_cast<const float4*>(base + 2 * DIM);
            }
        }

        {
            MBAR_WAIT(mb_s, t & 1);
            TC_FENCE_AFTER();
            const int wg = tid >> 7;
            const uint32_t cbase = TS + wg * 64;
            const uint32_t woff = (uint32_t)((tid & 127) >> 5) << 21;
            uint32_t s0[32], s1[32];
            TMEM_LDX32(s0, cbase);
            TMEM_LDX32(s1, cbase + 32);
            TC_WAIT_LD();
            #pragma unroll
            for (int k = 0; k < 32; k++) {
                float p = __expf(__uint_as_float(s0[k]));
                lsum += p;
                s0[k] = __float_as_uint(f2tf32(p));
            }
            #pragma unroll
            for (int k = 0; k < 32; k++) {
                float p = __expf(__uint_as_float(s1[k]));
                lsum += p;
                s1[k] = __float_as_uint(f2tf32(p));
            }
            TMEM_STX32(cbase + woff, s0);
            TMEM_STX32(cbase + 32 + woff, s1);
            TC_WAIT_ST();
            TC_FENCE_BEFORE();
        }
        __syncthreads();

        if (tid < 32) {
            if (elect_one()) {
                TC_FENCE_AFTER();
                #pragma unroll
                for (int s = 0; s < 16; s++) {
                    uint64_t bd = make_desc_sw128(smb + AV_OFF(buf) + (s >> 2) * 8192)
                                + (uint64_t)(s & 3) * 2;
                    mma_tf32_ts(TO, TS + s * 8, bd, idescO, (t | s) != 0);
                }
                TC_COMMIT(mb_o);
            }
        }
    }

    s_l[tid] = lsum;
    __syncthreads();
    MBAR_WAIT(mb_o, 7 & 1);
    TC_FENCE_AFTER();
    {
        const int row = tid & 127;
        const int wg  = tid >> 7;
        const float inv = 1.f / (s_l[row] + s_l[128 + row]);
        uint32_t o0[32];
        TMEM_LDX32(o0, TO + wg * 32);
        TC_WAIT_LD();
        float* op = out + (tokQ + row) * (size_t)DIM + h * HDIM + wg * 32;
        #pragma unroll
        for (int c = 0; c < 32; c += 4) {
            float4 v;
            v.x = __uint_as_float(o0[c + 0]) * inv;
            v.y = __uint_as_float(o0[c + 1]) * inv;
            v.z = __uint_as_float(o0[c + 2]) * inv;
            v.w = __uint_as_float(o0[c + 3]) * inv;
            *reinterpret_cast<float4*>(op + c) = v;
        }
    }
    __syncthreads();
    if (tid < 32) {
        TC_RELINQ();
        TC_DEALLOC(tmem, 256);
    }
#endif // HAS_TCGEN05
}

// ---------------------------------------------------------------------------
extern "C" void kernel_launch(void* const* d_in, const int* in_sizes, int n_in,
                              void* d_out, int out_size)
{
    const float* inp    = (const float*)d_in[0];   // [8,1024,1024]
    const float* w_qkv  = (const float*)d_in[1];   // [1024,3072]
    const float* b_qkv  = (const float*)d_in[2];   // [3072]
    const float* w_proj = (const float*)d_in[3];   // [1024,1024]
    const float* b_proj = (const float*)d_in[4];   // [1024]
    float* out = (float*)d_out;                    // [8,1024,1024]

    float *qkv_ptr, *att_ptr, *wt_ptr;
    cudaGetSymbolAddress((void**)&qkv_ptr, g_qkv);
    cudaGetSymbolAddress((void**)&att_ptr, g_att);
    cudaGetSymbolAddress((void**)&wt_ptr,  g_wt);
    float* wqkvT  = wt_ptr;                           // [3072][1024]
    float* wprojT = wt_ptr + (size_t)QKV_COLS * DIM;  // [1024][1024]

    cudaFuncSetAttribute(gemm_tc_tf32,
                         cudaFuncAttributeMaxDynamicSharedMemorySize,
                         GEMM_SMEM);
    cudaFuncSetAttribute(attn_tc,
                         cudaFuncAttributeMaxDynamicSharedMemorySize,
                         ATT_SMEM);

    // 0) pre-transpose weights to [N][K] tf32
    {
        dim3 g1(QKV_COLS / 32, DIM / 32);
        transpose_tf32<<<g1, 256>>>(w_qkv, wqkvT, DIM, QKV_COLS);
        dim3 g2(DIM / 32, DIM / 32);
        transpose_tf32<<<g2, 256>>>(w_proj, wprojT, DIM, DIM);
    }
    // 1) QKV GEMM: tiles 128x256
    {
        dim3 grid(QKV_COLS / BN, M_TOK / BM);
        gemm_tc_tf32<<<grid, 256, GEMM_SMEM>>>(inp, wqkvT, b_qkv, qkv_ptr,
                                               M_TOK, QKV_COLS, DIM);
    }
    // 2) attention
    {
        dim3 grid(SEQ / 128, NHEADS, BATCH);
        attn_tc<<<grid, 256, ATT_SMEM>>>(qkv_ptr, att_ptr);
    }
    // 3) projection: tiles 128x256
    {
        dim3 grid(DIM / BN, M_TOK / BM);
        gemm_tc_tf32<<<grid, 256, GEMM_SMEM>>>(att_ptr, wprojT, b_proj, out,
                                               M_TOK, DIM, DIM);
    }
}

// round 16
// speedup vs baseline: 1.2780x; 1.2780x over previous
#include <cuda_runtime.h>
#include <cuda.h>
#include <cuda_bf16.h>
#include <math.h>
#include <stdint.h>

// Problem constants
#define BATCH 8
#define SEQ 1024
#define DIM 1024
#define NHEADS 16
#define HDIM 64
#define M_TOK (BATCH * SEQ)        // 8192
#define QKV_COLS (3 * DIM)         // 3072
#define ATT_SCALE 0.125f           // 64^-0.5

#if defined(__CUDA_ARCH__) && defined(__CUDA_ARCH_FEAT_SM103_ALL)
#define HAS_TCGEN05 1
#else
#define HAS_TCGEN05 0
#endif

// Scratch (allocation-free rule: __device__ globals)
__device__ float g_qkv[(size_t)M_TOK * QKV_COLS];        // 96 MB
__device__ float g_att[(size_t)M_TOK * DIM];             // 32 MB (tf32-rounded)
__device__ float g_inp[(size_t)M_TOK * DIM];             // 32 MB (tf32-rounded)
__device__ float g_wt[(size_t)(QKV_COLS + DIM) * DIM];   // 16 MB: wqkvT | wprojT

// ===========================================================================
// tcgen05 helpers
// ===========================================================================
__device__ __forceinline__ uint32_t smem_u32(const void* p) {
    uint32_t a;
    asm("{ .reg .u64 t; cvta.to.shared.u64 t, %1; cvt.u32.u64 %0, t; }"
        : "=r"(a) : "l"(p));
    return a;
}

__device__ __forceinline__ uint32_t elect_one() {
    uint32_t pred;
    asm volatile(
        "{\n\t.reg .pred p;\n\t"
        "elect.sync _|p, 0xFFFFFFFF;\n\t"
        "selp.b32 %0, 1, 0, p;\n\t}"
        : "=r"(pred));
    return pred;
}

// SW128 K-major smem descriptor: layout=SW128(2), version=1, SBO=64, LBO=1
__device__ __forceinline__ uint64_t make_desc_sw128(uint32_t addr) {
    const uint64_t base =
        (uint64_t(2) << 61) | (uint64_t(1) << 46) |
        (uint64_t(64) << 32) | (uint64_t(1) << 16);
    return base | ((uint64_t)(addr >> 4) & 0x3FFF);
}

#define SWZ128(off) ((off) ^ (((off) >> 3) & 0x70))

#if HAS_TCGEN05
__device__ __forceinline__ void mma_tf32_ss(uint32_t d, uint64_t ad, uint64_t bd,
                                            uint32_t idesc, uint32_t en) {
    asm volatile(
        "{\n\t.reg .pred p;\n\t"
        "setp.ne.u32 p, %5, 0;\n\t"
        "tcgen05.mma.cta_group::1.kind::tf32 [%0], %1, %2, %3, {%4,%4,%4,%4}, p;\n\t"
        "}"
        :: "r"(d), "l"(ad), "l"(bd), "r"(idesc), "r"(0u), "r"(en)
        : "memory");
}

__device__ __forceinline__ void mma_tf32_ts(uint32_t d, uint32_t at, uint64_t bd,
                                            uint32_t idesc, uint32_t en) {
    asm volatile(
        "{\n\t.reg .pred p;\n\t"
        "setp.ne.u32 p, %5, 0;\n\t"
        "tcgen05.mma.cta_group::1.kind::tf32 [%0], [%1], %2, %3, {%4,%4,%4,%4}, p;\n\t"
        "}"
        :: "r"(d), "r"(at), "l"(bd), "r"(idesc), "r"(0u), "r"(en)
        : "memory");
}

#define TC_ALLOC(sm, n)  asm volatile("tcgen05.alloc.cta_group::1.sync.aligned.shared::cta.b32 [%0], %1;" :: "r"(sm), "r"((uint32_t)(n)) : "memory")
#define TC_DEALLOC(t, n) asm volatile("tcgen05.dealloc.cta_group::1.sync.aligned.b32 %0, %1;" :: "r"(t), "r"((uint32_t)(n)))
#define TC_RELINQ()      asm volatile("tcgen05.relinquish_alloc_permit.cta_group::1.sync.aligned;")
#define TC_COMMIT(mb)    asm volatile("tcgen05.commit.cta_group::1.mbarrier::arrive::one.shared::cluster.b64 [%0];" :: "r"(mb) : "memory")
#define TC_FENCE_BEFORE() asm volatile("tcgen05.fence::before_thread_sync;" ::: "memory")
#define TC_FENCE_AFTER() asm volatile("tcgen05.fence::after_thread_sync;" ::: "memory")
#define TC_WAIT_LD()     asm volatile("tcgen05.wait::ld.sync.aligned;" ::: "memory")
#define TC_WAIT_ST()     asm volatile("tcgen05.wait::st.sync.aligned;" ::: "memory")

#define TMEM_LDX32(r, ta)                                                   \
    asm volatile(                                                           \
        "tcgen05.ld.sync.aligned.32x32b.x32.b32 "                           \
        "{%0,%1,%2,%3,%4,%5,%6,%7,%8,%9,%10,%11,%12,%13,%14,%15,"           \
        "%16,%17,%18,%19,%20,%21,%22,%23,%24,%25,%26,%27,%28,%29,%30,%31}, [%32];" \
        : "=r"((r)[0]),"=r"((r)[1]),"=r"((r)[2]),"=r"((r)[3]),              \
          "=r"((r)[4]),"=r"((r)[5]),"=r"((r)[6]),"=r"((r)[7]),              \
          "=r"((r)[8]),"=r"((r)[9]),"=r"((r)[10]),"=r"((r)[11]),            \
          "=r"((r)[12]),"=r"((r)[13]),"=r"((r)[14]),"=r"((r)[15]),          \
          "=r"((r)[16]),"=r"((r)[17]),"=r"((r)[18]),"=r"((r)[19]),          \
          "=r"((r)[20]),"=r"((r)[21]),"=r"((r)[22]),"=r"((r)[23]),          \
          "=r"((r)[24]),"=r"((r)[25]),"=r"((r)[26]),"=r"((r)[27]),          \
          "=r"((r)[28]),"=r"((r)[29]),"=r"((r)[30]),"=r"((r)[31])           \
        : "r"(ta))

#define TMEM_STX32(ta, r)                                                   \
    asm volatile(                                                           \
        "tcgen05.st.sync.aligned.32x32b.x32.b32 [%0], "                     \
        "{%1,%2,%3,%4,%5,%6,%7,%8,%9,%10,%11,%12,%13,%14,%15,%16,"          \
        "%17,%18,%19,%20,%21,%22,%23,%24,%25,%26,%27,%28,%29,%30,%31,%32};" \
        :: "r"(ta),                                                         \
           "r"((r)[0]),"r"((r)[1]),"r"((r)[2]),"r"((r)[3]),                 \
           "r"((r)[4]),"r"((r)[5]),"r"((r)[6]),"r"((r)[7]),                 \
           "r"((r)[8]),"r"((r)[9]),"r"((r)[10]),"r"((r)[11]),               \
           "r"((r)[12]),"r"((r)[13]),"r"((r)[14]),"r"((r)[15]),             \
           "r"((r)[16]),"r"((r)[17]),"r"((r)[18]),"r"((r)[19]),             \
           "r"((r)[20]),"r"((r)[21]),"r"((r)[22]),"r"((r)[23]),             \
           "r"((r)[24]),"r"((r)[25]),"r"((r)[26]),"r"((r)[27]),             \
           "r"((r)[28]),"r"((r)[29]),"r"((r)[30]),"r"((r)[31])              \
        : "memory")

#define TMA_LOAD_2D(dst, map, cx, cy, mb)                                   \
    asm volatile(                                                           \
        "cp.async.bulk.tensor.2d.shared::cta.global.tile.mbarrier::complete_tx::bytes " \
        "[%0], [%1, {%2, %3}], [%4];"                                       \
        :: "r"(dst), "l"(map), "r"(cx), "r"(cy), "r"(mb) : "memory")
#endif // HAS_TCGEN05

#define MBAR_INIT(mb, n) asm volatile("mbarrier.init.shared.b64 [%0], %1;" :: "r"(mb), "r"((uint32_t)(n)) : "memory")
#define MBAR_EXPECT_TX(mb, bytes) asm volatile("mbarrier.arrive.expect_tx.shared.b64 _, [%0], %1;" :: "r"(mb), "r"((uint32_t)(bytes)) : "memory")
#define FENCE_PROXY()    asm volatile("fence.proxy.async.shared::cta;" ::: "memory")

#define MBAR_WAIT(mb, ph) do {                                              \
    uint32_t _m = (mb), _p = (ph), _done;                                   \
    asm volatile(                                                           \
        "{\n\t.reg .pred p;\n\t"                                            \
        "mbarrier.try_wait.parity.acquire.cta.shared::cta.b64 p, [%1], %2;\n\t" \
        "selp.b32 %0, 1, 0, p;\n\t}"                                        \
        : "=r"(_done) : "r"(_m), "r"(_p) : "memory");                       \
    if (!_done) {                                                           \
        asm volatile(                                                       \
            "{\n\t.reg .pred P1;\n\t"                                       \
            "WL_%=:\n\t"                                                    \
            "mbarrier.try_wait.parity.acquire.cta.shared::cta.b64 P1, [%0], %1, 0x989680;\n\t" \
            "@P1 bra.uni WD_%=;\n\t"                                        \
            "bra.uni WL_%=;\n\t"                                            \
            "WD_%=:\n\t}"                                                   \
            :: "r"(_m), "r"(_p) : "memory");                                \
    }                                                                       \
} while (0)

__device__ __forceinline__ float f2tf32(float v) {
    unsigned int u;
    asm volatile("cvt.rna.tf32.f32 %0, %1;" : "=r"(u) : "f"(v));
    return __uint_as_float(u);
}

// ===========================================================================
// Pre-passes
// ===========================================================================
__global__ __launch_bounds__(256) void transpose_tf32(
    const float* __restrict__ W, float* __restrict__ WT, int K, int N)
{
    __shared__ float tile[32][33];
    const int n0 = blockIdx.x * 32;
    const int k0 = blockIdx.y * 32;
    const int tx = threadIdx.x & 31;
    const int ty = threadIdx.x >> 5;

    #pragma unroll
    for (int i = ty; i < 32; i += 8)
        tile[i][tx] = W[(size_t)(k0 + i) * N + n0 + tx];
    __syncthreads();
    #pragma unroll
    for (int i = ty; i < 32; i += 8)
        WT[(size_t)(n0 + i) * K + k0 + tx] = f2tf32(tile[tx][i]);
}

__global__ __launch_bounds__(256) void cvt_tf32(
    const float* __restrict__ in, float* __restrict__ outp, size_t n4)
{
    size_t i = (size_t)blockIdx.x * 256 + threadIdx.x;
    size_t stride = (size_t)gridDim.x * 256;
    for (; i < n4; i += stride) {
        float4 v = reinterpret_cast<const float4*>(in)[i];
        v.x = f2tf32(v.x); v.y = f2tf32(v.y);
        v.z = f2tf32(v.z); v.w = f2tf32(v.w);
        reinterpret_cast<float4*>(outp)[i] = v;
    }
}

// ===========================================================================
// All-TMA tcgen05 tf32 GEMM (primary path). Tile 128x256, BK=64.
// ===========================================================================
#define BM 128
#define BN 256
#define GBK 64
#define STAGE_BYTES 98304
#define SA_OFF(buf) ((buf) * STAGE_BYTES)
#define SB_OFF(buf) ((buf) * STAGE_BYTES + 32768)
#define GEMM_SMEM 196608
#define NCH 16

__global__ __launch_bounds__(256, 1) __cluster_dims__(1, 1, 1)
void gemm_tma_tf32(const __grid_constant__ CUtensorMap mapA,
                   const __grid_constant__ CUtensorMap mapB,
                   const float* __restrict__ bias, float* __restrict__ C,
                   int N)
{
#if HAS_TCGEN05
    extern __shared__ __align__(1024) char dsm[];
    __shared__ uint32_t s_tmem;
    __shared__ __align__(8) uint64_t s_full[2];
    __shared__ __align__(8) uint64_t s_mma[2];

    const int tid = threadIdx.x;
    const int brow = blockIdx.y * BM;
    const int bcol = blockIdx.x * BN;
    const uint32_t smb = smem_u32(dsm);
    uint32_t mb_full[2] = { smem_u32(&s_full[0]), smem_u32(&s_full[1]) };
    uint32_t mb_mma[2]  = { smem_u32(&s_mma[0]),  smem_u32(&s_mma[1])  };

    if (tid < 32) TC_ALLOC(smem_u32(&s_tmem), 256);
    if (tid == 0) {
        MBAR_INIT(mb_full[0], 1); MBAR_INIT(mb_full[1], 1);
        MBAR_INIT(mb_mma[0], 1);  MBAR_INIT(mb_mma[1], 1);
        FENCE_PROXY();
    }
    __syncthreads();
    const uint32_t TD = s_tmem;

    const uint32_t idesc = (1u << 4) | (2u << 7) | (2u << 10)
                         | ((BN / 8) << 17) | ((BM / 16) << 24);

    if (tid == 0) {
        for (int ch = 0; ch < NCH; ch++) {
            const int buf = ch & 1;
            if (ch >= 2) MBAR_WAIT(mb_mma[buf], ((ch >> 1) - 1) & 1);
            MBAR_EXPECT_TX(mb_full[buf], STAGE_BYTES);
            const int k0 = ch * GBK;
            TMA_LOAD_2D(smb + SA_OFF(buf),         &mapA, k0,      brow, mb_full[buf]);
            TMA_LOAD_2D(smb + SA_OFF(buf) + 16384, &mapA, k0 + 32, brow, mb_full[buf]);
            TMA_LOAD_2D(smb + SB_OFF(buf),         &mapB, k0,      bcol, mb_full[buf]);
            TMA_LOAD_2D(smb + SB_OFF(buf) + 32768, &mapB, k0 + 32, bcol, mb_full[buf]);
        }
    } else if (tid == 32) {
        for (int ch = 0; ch < NCH; ch++) {
            const int buf = ch & 1;
            MBAR_WAIT(mb_full[buf], (ch >> 1) & 1);
            #pragma unroll
            for (int s = 0; s < 8; s++) {
                uint64_t ad = make_desc_sw128(smb + SA_OFF(buf) + (s >> 2) * 16384)
                            + (uint64_t)(s & 3) * 2;
                uint64_t bd = make_desc_sw128(smb + SB_OFF(buf) + (s >> 2) * 32768)
                            + (uint64_t)(s & 3) * 2;
                mma_tf32_ss(TD, ad, bd, idesc, (ch | s) != 0);
            }
            TC_COMMIT(mb_mma[buf]);
        }
    }
    __syncthreads();

    MBAR_WAIT(mb_mma[(NCH - 1) & 1], ((NCH - 1) >> 1) & 1);
    TC_FENCE_AFTER();

    {
        const int row = tid & 127;
        const int wh  = tid >> 7;
        const int crow = brow + row;
        #pragma unroll
        for (int c0 = 0; c0 < 128; c0 += 32) {
            uint32_t d[32];
            TMEM_LDX32(d, TD + wh * 128 + c0);
            TC_WAIT_LD();
            const int cb = bcol + wh * 128 + c0;
            #pragma unroll
            for (int c = 0; c < 32; c += 4) {
                float4 v;
                v.x = __uint_as_float(d[c + 0]) + bias[cb + c + 0];
                v.y = __uint_as_float(d[c + 1]) + bias[cb + c + 1];
                v.z = __uint_as_float(d[c + 2]) + bias[cb + c + 2];
                v.w = __uint_as_float(d[c + 3]) + bias[cb + c + 3];
                *reinterpret_cast<float4*>(C + (size_t)crow * N + cb + c) = v;
            }
        }
    }
    __syncthreads();
    if (tid < 32) {
        TC_RELINQ();
        TC_DEALLOC(TD, 256);
    }
#endif // HAS_TCGEN05
}

// ===========================================================================
// Fallback GEMM (round-7 proven): LDG staging, tiles 128x128, BK=64.
// ===========================================================================
#define FBM 128
#define FBN 128
#define FBK 64
#define FA0 0
#define FA1 32768
#define FB0 65536
#define FB1 98304
#define FGEMM_SMEM 131072

__global__ __launch_bounds__(256, 1) __cluster_dims__(1, 1, 1)
void gemm_ss_tf32(const float* __restrict__ A, const float* __restrict__ BT,
                  const float* __restrict__ bias, float* __restrict__ C,
                  int M, int N, int K)
{
#if HAS_TCGEN05
    extern __shared__ __align__(1024) char dsm[];
    __shared__ uint32_t s_tmem;
    __shared__ __align__(8) uint64_t s_mbar[2];

    const int tid = threadIdx.x;
    const int brow = blockIdx.y * FBM;
    const int bcol = blockIdx.x * FBN;
    const uint32_t smb = smem_u32(dsm);
    const uint32_t mbar0 = smem_u32(&s_mbar[0]);
    const uint32_t mbar1 = smem_u32(&s_mbar[1]);

    if (tid < 32) TC_ALLOC(smem_u32(&s_tmem), 128);
    if (tid == 0) { MBAR_INIT(mbar0, 1); MBAR_INIT(mbar1, 1); }
    __syncthreads();
    const uint32_t tmem = s_tmem;

    const uint32_t idesc = (1u << 4) | (2u << 7) | (2u << 10)
                         | ((FBN / 8) << 17) | ((FBM / 16) << 24);
    const int nch = K / FBK;   // 16

    int rr[8], cc[8];
    uint32_t soff[8];
    #pragma unroll
    for (int i = 0; i < 8; i++) {
        int id = i * 256 + tid;
        int r = id >> 4;
        int c = (id & 15) * 4;
        rr[i] = r; cc[i] = c;
        uint32_t off = (uint32_t)(((c >> 5) * 16 + (r >> 3)) * 1024
                                  + (r & 7) * 128 + (c & 31) * 4);
        soff[i] = SWZ128(off);
    }

    float4 av[8], bv[8];
    #pragma unroll
    for (int i = 0; i < 8; i++) {
        av[i] = *reinterpret_cast<const float4*>(
            A + (size_t)(brow + rr[i]) * K + cc[i]);
        bv[i] = *reinterpret_cast<const float4*>(
            BT + (size_t)(bcol + rr[i]) * K + cc[i]);
    }

    for (int ch = 0; ch < nch; ch++) {
        const int b = ch & 1;
        const uint32_t abuf = smb + (b ? FA1 : FA0);
        const uint32_t bbuf = smb + (b ? FB1 : FB0);

        if (ch >= 2) MBAR_WAIT(b ? mbar1 : mbar0, ((ch >> 1) - 1) & 1);

        #pragma unroll
        for (int i = 0; i < 8; i++) {
            asm volatile("st.shared.v4.b32 [%0], {%1,%2,%3,%4};"
                :: "r"(abuf + soff[i]),
                   "r"(__float_as_uint(f2tf32(av[i].x))),
                   "r"(__float_as_uint(f2tf32(av[i].y))),
                   "r"(__float_as_uint(f2tf32(av[i].z))),
                   "r"(__float_as_uint(f2tf32(av[i].w))) : "memory");
            asm volatile("st.shared.v4.b32 [%0], {%1,%2,%3,%4};"
                :: "r"(bbuf + soff[i]),
                   "r"(__float_as_uint(bv[i].x)), "r"(__float_as_uint(bv[i].y)),
                   "r"(__float_as_uint(bv[i].z)), "r"(__float_as_uint(bv[i].w))
                : "memory");
        }

        if (ch + 1 < nch) {
            const int k0 = (ch + 1) * FBK;
            #pragma unroll
            for (int i = 0; i < 8; i++) {
                av[i] = *reinterpret_cast<const float4*>(
                    A + (size_t)(brow + rr[i]) * K + k0 + cc[i]);
                bv[i] = *reinterpret_cast<const float4*>(
                    BT + (size_t)(bcol + rr[i]) * K + k0 + cc[i]);
            }
        }

        FENCE_PROXY();
        __syncthreads();

        if (tid < 32) {
            if (elect_one()) {
                uint64_t ad = make_desc_sw128(abuf);
                uint64_t bd = make_desc_sw128(bbuf);
                #pragma unroll
                for (int s = 0; s < 8; s++) {
                    uint64_t dso = (uint64_t)((s & 3) * 2 + (s >> 2) * 1024);
                    mma_tf32_ss(tmem, ad + dso, bd + dso, idesc, (ch | s) != 0);
                }
                TC_COMMIT(b ? mbar1 : mbar0);
            }
        }
    }

    {
        const int last = nch - 1;
        MBAR_WAIT((last & 1) ? mbar1 : mbar0, (last >> 1) & 1);
    }
    TC_FENCE_AFTER();

    if (tid < 128) {
        const int wid = tid >> 5;
        const int lane = tid & 31;
        const int row = brow + wid * 32 + lane;
        #pragma unroll
        for (int c0 = 0; c0 < FBN; c0 += 32) {
            uint32_t d[32];
            TMEM_LDX32(d, tmem + c0);
            TC_WAIT_LD();
            #pragma unroll
            for (int c = 0; c < 32; c += 4) {
                float4 v;
                v.x = __uint_as_float(d[c + 0]) + bias[bcol + c0 + c + 0];
                v.y = __uint_as_float(d[c + 1]) + bias[bcol + c0 + c + 1];
                v.z = __uint_as_float(d[c + 2]) + bias[bcol + c0 + c + 2];
                v.w = __uint_as_float(d[c + 3]) + bias[bcol + c0 + c + 3];
                *reinterpret_cast<float4*>(C + (size_t)row * N + bcol + c0 + c) = v;
            }
        }
    }
    __syncthreads();
    if (tid < 32) {
        TC_RELINQ();
        TC_DEALLOC(tmem, 128);
    }
#endif // HAS_TCGEN05
}

// ===========================================================================
// Tensor-core flash attention (round-11 structure, 166us proven; tf32 output)
// ===========================================================================
#define AQ_OFF 0
#define AK_OFF(buf) (32768 + (buf) * 32768)
#define AV_OFF(buf) (98304 + (buf) * 32768)
#define ATT_SMEM 163840

__global__ __launch_bounds__(256, 1) __cluster_dims__(1, 1, 1)
void attn_tc(const float* __restrict__ qkv, float* __restrict__ out)
{
#if HAS_TCGEN05
    extern __shared__ __align__(1024) char dsm[];
    __shared__ uint32_t s_tmem;
    __shared__ __align__(8) uint64_t s_mb[2];
    __shared__ float s_l[256];

    const int tid = threadIdx.x;
    const int qt = blockIdx.x;
    const int h  = blockIdx.y;
    const int b  = blockIdx.z;
    const uint32_t smb = smem_u32(dsm);
    const uint32_t mb_s = smem_u32(&s_mb[0]);
    const uint32_t mb_o = smem_u32(&s_mb[1]);

    if (tid < 32) TC_ALLOC(smem_u32(&s_tmem), 256);
    if (tid == 0) { MBAR_INIT(mb_s, 1); MBAR_INIT(mb_o, 1); }
    __syncthreads();
    const uint32_t tmem = s_tmem;
    const uint32_t TS = tmem;
    const uint32_t TO = tmem + 128;

    const size_t tokQ = (size_t)b * SEQ + qt * 128;
    const size_t tokB = (size_t)b * SEQ;

    const uint32_t idescS = (1u << 4) | (2u << 7) | (2u << 10)
                          | (16u << 17) | (8u << 24);
    const uint32_t idescO = (1u << 4) | (2u << 7) | (2u << 10)
                          | (8u << 17) | (8u << 24);

    int rI[8], cI[8];
    #pragma unroll
    for (int i = 0; i < 8; i++) {
        int id = i * 256 + tid;
        rI[i] = id >> 4;
        cI[i] = (id & 15) * 4;
    }

    #pragma unroll
    for (int i = 0; i < 8; i++) {
        float4 v = *reinterpret_cast<const float4*>(
            qkv + (tokQ + rI[i]) * QKV_COLS + h * HDIM + cI[i]);
        uint32_t off = AQ_OFF + (cI[i] >> 5) * 16384
                     + SWZ128((uint32_t)(rI[i] * 128 + (cI[i] & 31) * 4));
        asm volatile("st.shared.v4.b32 [%0], {%1,%2,%3,%4};"
            :: "r"(smb + off),
               "r"(__float_as_uint(f2tf32(v.x * ATT_SCALE))),
               "r"(__float_as_uint(f2tf32(v.y * ATT_SCALE))),
               "r"(__float_as_uint(f2tf32(v.z * ATT_SCALE))),
               "r"(__float_as_uint(f2tf32(v.w * ATT_SCALE))) : "memory");
    }

    float4 kreg[8], vreg[8];
    #pragma unroll
    for (int i = 0; i < 8; i++) {
        const float* base = qkv + (tokB + rI[i]) * QKV_COLS + h * HDIM + cI[i];
        kreg[i] = *reinterpret_cast<const float4*>(base + DIM);
        vreg[i] = *reinterpret_cast<const float4*>(base + 2 * DIM);
    }

    float lsum = 0.f;

    for (int t = 0; t < 8; t++) {
        const int buf = t & 1;

        #pragma unroll
        for (int i = 0; i < 8; i++) {
            uint32_t koff = AK_OFF(buf) + (cI[i] >> 5) * 16384
                          + SWZ128((uint32_t)(rI[i] * 128 + (cI[i] & 31) * 4));
            asm volatile("st.shared.v4.b32 [%0], {%1,%2,%3,%4};"
                :: "r"(smb + koff),
                   "r"(__float_as_uint(f2tf32(kreg[i].x))),
                   "r"(__float_as_uint(f2tf32(kreg[i].y))),
                   "r"(__float_as_uint(f2tf32(kreg[i].z))),
                   "r"(__float_as_uint(f2tf32(kreg[i].w))) : "memory");
            uint32_t kb  = (rI[i] >> 5) * 8192;
            uint32_t kc4 = (rI[i] & 31) * 4;
            uint32_t o0 = AV_OFF(buf) + kb + SWZ128((uint32_t)((cI[i] + 0) * 128 + kc4));
            uint32_t o1 = AV_OFF(buf) + kb + SWZ128((uint32_t)((cI[i] + 1) * 128 + kc4));
            uint32_t o2 = AV_OFF(buf) + kb + SWZ128((uint32_t)((cI[i] + 2) * 128 + kc4));
            uint32_t o3 = AV_OFF(buf) + kb + SWZ128((uint32_t)((cI[i] + 3) * 128 + kc4));
            asm volatile("st.shared.b32 [%0], %1;" :: "r"(smb + o0),
                         "r"(__float_as_uint(f2tf32(vreg[i].x))) : "memory");
            asm volatile("st.shared.b32 [%0], %1;" :: "r"(smb + o1),
                         "r"(__float_as_uint(f2tf32(vreg[i].y))) : "memory");
            asm volatile("st.shared.b32 [%0], %1;" :: "r"(smb + o2),
                         "r"(__float_as_uint(f2tf32(vreg[i].z))) : "memory");
            asm volatile("st.shared.b32 [%0], %1;" :: "r"(smb + o3),
                         "r"(__float_as_uint(f2tf32(vreg[i].w))) : "memory");
        }
        FENCE_PROXY();
        __syncthreads();

        if (tid < 32) {
            if (t > 0) MBAR_WAIT(mb_o, (t - 1) & 1);
            if (elect_one()) {
                #pragma unroll
                for (int s = 0; s < 8; s++) {
                    uint64_t ad = make_desc_sw128(smb + AQ_OFF + (s >> 2) * 16384)
                                + (uint64_t)(s & 3) * 2;
                    uint64_t bd = make_desc_sw128(smb + AK_OFF(buf) + (s >> 2) * 16384)
                                + (uint64_t)(s & 3) * 2;
                    mma_tf32_ss(TS, ad, bd, idescS, s != 0);
                }
                TC_COMMIT(mb_s);
            }
        }

        if (t + 1 < 8) {
            #pragma unroll
            for (int i = 0; i < 8; i++) {
                const float* base = qkv + (tokB + (t + 1) * 128 + rI[i]) * QKV_COLS
                                  + h * HDIM + cI[i];
                kreg[i] = *reinterpret_cast<const float4*>(base + DIM);
                vreg[i] = *reinterpret_cast<const float4*>(base + 2 * DIM);
            }
        }

        {
            MBAR_WAIT(mb_s, t & 1);
            TC_FENCE_AFTER();
            const int wg = tid >> 7;
            const uint32_t cbase = TS + wg * 64;
            const uint32_t woff = (uint32_t)((tid & 127) >> 5) << 21;
            uint32_t s0[32], s1[32];
            TMEM_LDX32(s0, cbase);
            TMEM_LDX32(s1, cbase + 32);
            TC_WAIT_LD();
            #pragma unroll
            for (int k = 0; k < 32; k++) {
                float p = __expf(__uint_as_float(s0[k]));
                lsum += p;
                s0[k] = __float_as_uint(f2tf32(p));
            }
            #pragma unroll
            for (int k = 0; k < 32; k++) {
                float p = __expf(__uint_as_float(s1[k]));
                lsum += p;
                s1[k] = __float_as_uint(f2tf32(p));
            }
            TMEM_STX32(cbase + woff, s0);
            TMEM_STX32(cbase + 32 + woff, s1);
            TC_WAIT_ST();
            TC_FENCE_BEFORE();
        }
        __syncthreads();

        if (tid < 32) {
            if (elect_one()) {
                TC_FENCE_AFTER();
                #pragma unroll
                for (int s = 0; s < 16; s++) {
                    uint64_t bd = make_desc_sw128(smb + AV_OFF(buf) + (s >> 2) * 8192)
                                + (uint64_t)(s & 3) * 2;
                    mma_tf32_ts(TO, TS + s * 8, bd, idescO, (t | s) != 0);
                }
                TC_COMMIT(mb_o);
            }
        }
    }

    s_l[tid] = lsum;
    __syncthreads();
    MBAR_WAIT(mb_o, 7 & 1);
    TC_FENCE_AFTER();
    {
        const int row = tid & 127;
        const int wg  = tid >> 7;
        const float inv = 1.f / (s_l[row] + s_l[128 + row]);
        uint32_t o0[32];
        TMEM_LDX32(o0, TO + wg * 32);
        TC_WAIT_LD();
        float* op = out + (tokQ + row) * (size_t)DIM + h * HDIM + wg * 32;
        #pragma unroll
        for (int c = 0; c < 32; c += 4) {
            float4 v;
            v.x = f2tf32(__uint_as_float(o0[c + 0]) * inv);
            v.y = f2tf32(__uint_as_float(o0[c + 1]) * inv);
            v.z = f2tf32(__uint_as_float(o0[c + 2]) * inv);
            v.w = f2tf32(__uint_as_float(o0[c + 3]) * inv);
            *reinterpret_cast<float4*>(op + c) = v;
        }
    }
    __syncthreads();
    if (tid < 32) {
        TC_RELINQ();
        TC_DEALLOC(tmem, 256);
    }
#endif // HAS_TCGEN05
}

// ---------------------------------------------------------------------------
// Host
// ---------------------------------------------------------------------------
typedef CUresult (*EncFnT)(
    CUtensorMap*, CUtensorMapDataType, cuuint32_t, void*,
    const cuuint64_t*, const cuuint64_t*, const cuuint32_t*, const cuuint32_t*,
    CUtensorMapInterleave, CUtensorMapSwizzle, CUtensorMapL2promotion,
    CUtensorMapFloatOOBfill);

static bool encode_map(EncFnT enc, CUtensorMap* m, void* ptr,
                       uint64_t kdim, uint64_t rows, uint32_t boxRows)
{
    cuuint64_t dims[2]    = { kdim, rows };
    cuuint64_t strides[1] = { kdim * sizeof(float) };
    cuuint32_t box[2]     = { 32u, boxRows };
    cuuint32_t elem[2]    = { 1u, 1u };
    CUresult r = enc(m, CU_TENSOR_MAP_DATA_TYPE_FLOAT32, 2, ptr, dims, strides,
                     box, elem, CU_TENSOR_MAP_INTERLEAVE_NONE,
                     CU_TENSOR_MAP_SWIZZLE_128B,
                     CU_TENSOR_MAP_L2_PROMOTION_L2_128B,
                     CU_TENSOR_MAP_FLOAT_OOB_FILL_NONE);
    return r == CUDA_SUCCESS;
}

extern "C" void kernel_launch(void* const* d_in, const int* in_sizes, int n_in,
                              void* d_out, int out_size)
{
    const float* inp    = (const float*)d_in[0];   // [8,1024,1024]
    const float* w_qkv  = (const float*)d_in[1];   // [1024,3072]
    const float* b_qkv  = (const float*)d_in[2];   // [3072]
    const float* w_proj = (const float*)d_in[3];   // [1024,1024]
    const float* b_proj = (const float*)d_in[4];   // [1024]
    float* out = (float*)d_out;                    // [8,1024,1024]

    float *qkv_ptr, *att_ptr, *wt_ptr, *inp_ptr;
    cudaGetSymbolAddress((void**)&qkv_ptr, g_qkv);
    cudaGetSymbolAddress((void**)&att_ptr, g_att);
    cudaGetSymbolAddress((void**)&wt_ptr,  g_wt);
    cudaGetSymbolAddress((void**)&inp_ptr, g_inp);
    float* wqkvT  = wt_ptr;                           // [3072][1024]
    float* wprojT = wt_ptr + (size_t)QKV_COLS * DIM;  // [1024][1024]

    // Resolve driver tensormap encoder (guarded — NULL means fallback path).
    EncFnT enc = nullptr;
    {
        void* fn = nullptr;
        cudaDriverEntryPointQueryResult qr = cudaDriverEntryPointSymbolNotFound;
        cudaError_t e = cudaGetDriverEntryPoint("cuTensorMapEncodeTiled", &fn,
                                                cudaEnableDefault, &qr);
        if (e == cudaSuccess && qr == cudaDriverEntryPointSuccess && fn)
            enc = (EncFnT)fn;
    }

    CUtensorMap mapA_qkv, mapB_qkv, mapA_prj, mapB_prj;
    bool useTma = (enc != nullptr);
    if (useTma) {
        useTma = encode_map(enc, &mapA_qkv, inp_ptr, DIM, M_TOK,    128)
              && encode_map(enc, &mapB_qkv, wqkvT,   DIM, QKV_COLS, 256)
              && encode_map(enc, &mapA_prj, att_ptr, DIM, M_TOK,    128)
              && encode_map(enc, &mapB_prj, wprojT,  DIM, DIM,      256);
    }

    cudaFuncSetAttribute(gemm_tma_tf32,
                         cudaFuncAttributeMaxDynamicSharedMemorySize,
                         GEMM_SMEM);
    cudaFuncSetAttribute(gemm_ss_tf32,
                         cudaFuncAttributeMaxDynamicSharedMemorySize,
                         FGEMM_SMEM);
    cudaFuncSetAttribute(attn_tc,
                         cudaFuncAttributeMaxDynamicSharedMemorySize,
                         ATT_SMEM);

    // 0) pre-passes
    {
        dim3 g1(QKV_COLS / 32, DIM / 32);
        transpose_tf32<<<g1, 256>>>(w_qkv, wqkvT, DIM, QKV_COLS);
        dim3 g2(DIM / 32, DIM / 32);
        transpose_tf32<<<g2, 256>>>(w_proj, wprojT, DIM, DIM);
        if (useTma)
            cvt_tf32<<<512, 256>>>(inp, inp_ptr, (size_t)M_TOK * DIM / 4);
    }
    // 1) QKV GEMM
    if (useTma) {
        dim3 grid(QKV_COLS / BN, M_TOK / BM);
        gemm_tma_tf32<<<grid, 256, GEMM_SMEM>>>(mapA_qkv, mapB_qkv,
                                                b_qkv, qkv_ptr, QKV_COLS);
    } else {
        dim3 grid(QKV_COLS / FBN, M_TOK / FBM);
        gemm_ss_tf32<<<grid, 256, FGEMM_SMEM>>>(inp, wqkvT, b_qkv, qkv_ptr,
                                                M_TOK, QKV_COLS, DIM);
    }
    // 2) attention
    {
        dim3 grid(SEQ / 128, NHEADS, BATCH);
        attn_tc<<<grid, 256, ATT_SMEM>>>(qkv_ptr, att_ptr);
    }
    // 3) projection
    if (useTma) {
        dim3 grid(DIM / BN, M_TOK / BM);
        gemm_tma_tf32<<<grid, 256, GEMM_SMEM>>>(mapA_prj, mapB_prj,
                                                b_proj, out, DIM);
    } else {
        dim3 grid(DIM / FBN, M_TOK / FBM);
        gemm_ss_tf32<<<grid, 256, FGEMM_SMEM>>>(att_ptr, wprojT, b_proj, out,
                                                M_TOK, DIM, DIM);
    }
}